// round 4
// baseline (speedup 1.0000x reference)
#include <cuda_runtime.h>
#include <math.h>
#include <stdint.h>

#define FHH 32
#define FWW 88
#define NPIX 2816          // 32*88
#define NCAM 6
#define FCH 256            // conv channels
#define COUT 128           // BEV channels
#define ND 59              // depth bins
#define NVOX 16384         // 128*128 BEV cells

// ---------------- scratch (static device allocations) ----------------
__device__ __align__(16) float g_imgr[NCAM * FCH * NPIX];   // tf32-rounded input
__device__ __align__(16) float g_h1[NCAM * FCH * NPIX];
__device__ __align__(16) float g_h2[NCAM * FCH * NPIX];
__device__ __align__(16) float g_feat[NCAM * COUT * NPIX];
__device__ __align__(16) float g_w1t[9 * FCH * FCH];
__device__ __align__(16) float g_w2t[9 * FCH * FCH];
__device__ __align__(16) float g_w3t[FCH * COUT];
__device__ float g_scale1[FCH], g_scale2[FCH];
__device__ float g_beta1[FCH], g_beta2[FCH], g_beta3[COUT];
__device__ __align__(16) float g_bev[NVOX * COUT];   // [vox][c] channel-contiguous

// ---------------- helpers ----------------
__device__ __forceinline__ unsigned f2tf32(float x) {
    unsigned r;
    asm("cvt.rna.tf32.f32 %0, %1;" : "=r"(r) : "f"(x));
    return r;
}
__device__ __forceinline__ uint32_t smem_u32(const void* p) {
    uint32_t a;
    asm("{ .reg .u64 t; cvta.to.shared.u64 t, %1; cvt.u32.u64 %0, t; }" : "=r"(a) : "l"(p));
    return a;
}
__device__ __forceinline__ void cp16(uint32_t dst, const void* src) {
    asm volatile("cp.async.cg.shared.global [%0], [%1], 16;" :: "r"(dst), "l"(src));
}
__device__ __forceinline__ void cp4z(uint32_t dst, const void* src, int srcsize) {
    asm volatile("cp.async.ca.shared.global [%0], [%1], 4, %2;" :: "r"(dst), "l"(src), "r"(srcsize));
}
#define CP_COMMIT() asm volatile("cp.async.commit_group;" ::: "memory")
#define CP_WAIT1()  asm volatile("cp.async.wait_group 1;" ::: "memory")
#define CP_WAIT0()  asm volatile("cp.async.wait_group 0;" ::: "memory")

__device__ __forceinline__ void mma_tf32(float* d, const unsigned* a, unsigned b0, unsigned b1) {
    asm volatile(
        "mma.sync.aligned.m16n8k8.row.col.f32.tf32.tf32.f32 "
        "{%0,%1,%2,%3}, {%4,%5,%6,%7}, {%8,%9}, {%0,%1,%2,%3};\n"
        : "+f"(d[0]), "+f"(d[1]), "+f"(d[2]), "+f"(d[3])
        : "r"(a[0]), "r"(a[1]), "r"(a[2]), "r"(a[3]), "r"(b0), "r"(b1));
}

// ---------------- setup: fold BN into scale/beta ----------------
__global__ void setup_kernel(const float* __restrict__ c1b,
                             const float* __restrict__ g1, const float* __restrict__ b1,
                             const float* __restrict__ m1, const float* __restrict__ v1,
                             const float* __restrict__ c2b,
                             const float* __restrict__ g2, const float* __restrict__ b2,
                             const float* __restrict__ m2, const float* __restrict__ v2,
                             const float* __restrict__ c3b)
{
    int i = threadIdx.x;
    if (i < FCH) {
        float s1 = g1[i] * rsqrtf(v1[i] + 1e-3f);
        g_scale1[i] = s1;
        g_beta1[i] = (c1b[i] - m1[i]) * s1 + b1[i];
        float s2 = g2[i] * rsqrtf(v2[i] + 1e-3f);
        g_scale2[i] = s2;
        g_beta2[i] = (c2b[i] - m2[i]) * s2 + b2[i];
    }
    if (i < COUT) g_beta3[i] = c3b[i];
}

// ---------------- weight transforms: (Co,Ci,3,3)->[t][ci][co], scale folded, tf32-rounded ----------------
__global__ void wtrans3x3_kernel(const float* __restrict__ w,
                                 const float* __restrict__ scale,
                                 float* __restrict__ out)
{
    int idx = blockIdx.x * blockDim.x + threadIdx.x;
    if (idx >= 9 * FCH * FCH) return;
    int t  = idx / (FCH * FCH);
    int r  = idx % (FCH * FCH);
    int ci = r / FCH;
    int co = r % FCH;
    out[idx] = __uint_as_float(f2tf32(w[(co * FCH + ci) * 9 + t] * scale[co]));
}

__global__ void wtrans1x1_kernel(const float* __restrict__ w, float* __restrict__ out)
{
    int idx = blockIdx.x * blockDim.x + threadIdx.x;
    if (idx >= FCH * COUT) return;
    int ci = idx / COUT;
    int co = idx % COUT;
    out[idx] = __uint_as_float(f2tf32(w[co * FCH + ci]));
}

// ---------------- pre-round activations to tf32 ----------------
__global__ void round_img_kernel(const float* __restrict__ in, float* __restrict__ out)
{
    int i = blockIdx.x * blockDim.x + threadIdx.x;
    if (i >= NCAM * FCH * NPIX / 4) return;
    float4 v = ((const float4*)in)[i];
    float4 o;
    o.x = __uint_as_float(f2tf32(v.x));
    o.y = __uint_as_float(f2tf32(v.y));
    o.z = __uint_as_float(f2tf32(v.z));
    o.w = __uint_as_float(f2tf32(v.w));
    ((float4*)out)[i] = o;
}

// ---------------- implicit-GEMM conv via tf32 mma.sync, cp.async double-buffered ----------------
// Tile: BM=128 (co) x BN=128 (pixels), BK=32, 256 threads (8 warps, 2x4),
// warp tile 64x32 = 4x4 m16n8k8 mmas per k8-step. 2-stage smem pipeline.
// smem floats: As0 @0, Bs0 @4224, As1 @8448, Bs1 @12672; each tile 32 rows x 132 stride.
template <int TAPS, bool RELU, bool RND>
__global__ void __launch_bounds__(256, 2)
conv_kernel(const float* __restrict__ in_all, const float* __restrict__ wtt,
            const float* __restrict__ beta, float* __restrict__ out_all,
            int Cin, int Cout)
{
    extern __shared__ __align__(16) float smem[];
    const uint32_t sbase = smem_u32(smem);

    const int n   = blockIdx.z;
    const float* in  = in_all + (size_t)n * Cin * NPIX;
    float*       out = out_all + (size_t)n * Cout * NPIX;
    const int co0 = blockIdx.y * 128;
    const int p0  = blockIdx.x * 128;
    const int tid = threadIdx.x;
    const int lane = tid & 31;
    const int wid  = tid >> 5;
    const int wm0 = (wid & 1) * 64;
    const int wn0 = (wid >> 1) * 32;

    const int pnB = tid & 127;
    const int kkB = tid >> 7;          // 0 or 1
    const int p  = p0 + pnB;
    const int hh = p / FWW;
    const int ww = p % FWW;

    const int KIT = Cin / 32;
    const int S = TAPS * KIT;

    float acc[4][4][4];
#pragma unroll
    for (int mi = 0; mi < 4; mi++)
#pragma unroll
        for (int ni = 0; ni < 4; ni++)
#pragma unroll
            for (int r = 0; r < 4; r++) acc[mi][ni][r] = 0.f;

    auto load_stage = [&](int s, int buf) {
        const int t  = s / KIT;
        const int k0 = (s % KIT) * 32;
        const float* wt = wtt + (size_t)t * Cin * Cout;
        const uint32_t aoff = sbase + (buf ? 33792u : 0u);
        const uint32_t boff = sbase + (buf ? 50688u : 16896u);
        // A tile: 32 x 128, 16B cp.async, fully coalesced
#pragma unroll
        for (int i = 0; i < 4; i++) {
            int idx = tid + i * 256;
            int kk = idx >> 5;
            int c4 = idx & 31;
            cp16(aoff + (uint32_t)(kk * 528 + c4 * 16),
                 wt + (size_t)(k0 + kk) * Cout + co0 + c4 * 4);
        }
        // B tile: implicit-im2col, 4B cp.async with zero-fill on invalid taps
        bool valid;
        int srcoff;
        if (TAPS == 1) { valid = true; srcoff = p; }
        else {
            int dy = t / 3 - 1, dx = t % 3 - 1;
            int h2 = hh + dy, w2 = ww + dx;
            valid = (h2 >= 0) && (h2 < FHH) && (w2 >= 0) && (w2 < FWW);
            srcoff = valid ? h2 * FWW + w2 : 0;
        }
        const int sz = valid ? 4 : 0;
#pragma unroll
        for (int i = 0; i < 16; i++) {
            int kk = kkB + i * 2;
            cp4z(boff + (uint32_t)(kk * 528 + pnB * 4),
                 in + (size_t)(k0 + kk) * NPIX + srcoff, sz);
        }
    };

    load_stage(0, 0);
    CP_COMMIT();

    for (int s = 0; s < S; ++s) {
        const int buf = s & 1;
        if (s + 1 < S) {
            load_stage(s + 1, buf ^ 1);
            CP_COMMIT();
            CP_WAIT1();
        } else {
            CP_WAIT0();
        }
        __syncthreads();

        const float* As = smem + (buf ? 8448 : 0);
        const float* Bs = smem + (buf ? 12672 : 4224);

#pragma unroll
        for (int ks = 0; ks < 4; ks++) {
            const int kq = ks * 8 + (lane & 3);
            unsigned a[4][4];
#pragma unroll
            for (int mi = 0; mi < 4; mi++) {
                int m = wm0 + mi * 16 + (lane >> 2);
                a[mi][0] = __float_as_uint(As[kq * 132 + m]);
                a[mi][1] = __float_as_uint(As[kq * 132 + m + 8]);
                a[mi][2] = __float_as_uint(As[(kq + 4) * 132 + m]);
                a[mi][3] = __float_as_uint(As[(kq + 4) * 132 + m + 8]);
            }
#pragma unroll
            for (int ni = 0; ni < 4; ni++) {
                int nn = wn0 + ni * 8 + (lane >> 2);
                unsigned b0 = __float_as_uint(Bs[kq * 132 + nn]);
                unsigned b1 = __float_as_uint(Bs[(kq + 4) * 132 + nn]);
#pragma unroll
                for (int mi = 0; mi < 4; mi++)
                    mma_tf32(acc[mi][ni], a[mi], b0, b1);
            }
        }
        __syncthreads();
    }

    // epilogue: +beta, relu, optional tf32 rounding, float2 stores
#pragma unroll
    for (int mi = 0; mi < 4; mi++) {
        int r0 = co0 + wm0 + mi * 16 + (lane >> 2);
        int r1 = r0 + 8;
        float be0 = beta[r0];
        float be1 = beta[r1];
#pragma unroll
        for (int ni = 0; ni < 4; ni++) {
            int c = p0 + wn0 + ni * 8 + (lane & 3) * 2;
            float v0 = acc[mi][ni][0] + be0;
            float v1 = acc[mi][ni][1] + be0;
            float v2 = acc[mi][ni][2] + be1;
            float v3 = acc[mi][ni][3] + be1;
            if (RELU) {
                v0 = fmaxf(v0, 0.f); v1 = fmaxf(v1, 0.f);
                v2 = fmaxf(v2, 0.f); v3 = fmaxf(v3, 0.f);
            }
            if (RND) {
                v0 = __uint_as_float(f2tf32(v0));
                v1 = __uint_as_float(f2tf32(v1));
                v2 = __uint_as_float(f2tf32(v2));
                v3 = __uint_as_float(f2tf32(v3));
            }
            *(float2*)(out + (size_t)r0 * NPIX + c) = make_float2(v0, v1);
            *(float2*)(out + (size_t)r1 * NPIX + c) = make_float2(v2, v3);
        }
    }
}

// ---------------- zero the scratch BEV ----------------
__global__ void zero_bev_kernel()
{
    int idx = blockIdx.x * blockDim.x + threadIdx.x;
    float4 z = make_float4(0.f, 0.f, 0.f, 0.f);
    for (int i = idx; i < NVOX * COUT / 4; i += gridDim.x * blockDim.x)
        ((float4*)g_bev)[i] = z;
}

// ---------------- fused depth-softmax + lift + splat ----------------
__global__ void __launch_bounds__(128)
splat_kernel(const float* __restrict__ rel, const int* __restrict__ vox,
             const float* __restrict__ log_scale, const float* __restrict__ shift,
             const float* __restrict__ log_sigma, const float* __restrict__ feat)
{
    const int pb = blockIdx.x;
    const int n = pb / NPIX;
    const int p = pb % NPIX;
    const int tid = threadIdx.x;

    __shared__ float sw[ND];
    __shared__ int   sv[ND];
    __shared__ __align__(16) float sf[COUT];
    __shared__ float s_mx, s_inv;

    const float metric = fminf(fmaxf(expf(log_scale[0]) * rel[n * NPIX + p] + shift[0], 0.5f), 150.f);
    const float sigma  = fminf(fmaxf(expf(log_sigma[0]), 0.1f), 20.f);

    if (tid < ND) {
        sw[tid] = -fabsf(metric - (float)(tid + 1)) / sigma;
        sv[tid] = vox[(size_t)(n * ND + tid) * NPIX + p];
    }
    sf[tid] = feat[(size_t)(n * COUT + tid) * NPIX + p];
    __syncthreads();

    if (tid == 0) {
        float mx = -1e30f;
        for (int d = 0; d < ND; d++) mx = fmaxf(mx, sw[d]);
        float s = 0.f;
        for (int d = 0; d < ND; d++) s += expf(sw[d] - mx);
        s_mx = mx;
        s_inv = 1.f / s;
    }
    __syncthreads();
    if (tid < ND) sw[tid] = expf(sw[tid] - s_mx) * s_inv;
    __syncthreads();

    const int lane = tid & 31;
    const int wid  = tid >> 5;
    float4 f = *(const float4*)&sf[lane * 4];
    for (int d = wid; d < ND; d += 4) {
        float wg = sw[d];
        float4 v = make_float4(wg * f.x, wg * f.y, wg * f.z, wg * f.w);
        atomicAdd((float4*)&g_bev[(size_t)sv[d] * COUT + lane * 4], v);
    }
}

// ---------------- transpose [vox][c] -> output (C, X*Y) ----------------
__global__ void transpose_kernel(float* __restrict__ out)
{
    __shared__ float tile[32][33];
    int v0 = blockIdx.x * 32;
    int c0 = blockIdx.y * 32;
    int tx = threadIdx.x;
    int ty = threadIdx.y;
#pragma unroll
    for (int i = 0; i < 32; i += 8)
        tile[ty + i][tx] = g_bev[(size_t)(v0 + ty + i) * COUT + c0 + tx];
    __syncthreads();
#pragma unroll
    for (int i = 0; i < 32; i += 8)
        out[(size_t)(c0 + ty + i) * NVOX + v0 + tx] = tile[tx][ty + i];
}

// ---------------- launch ----------------
#define CONV_SMEM 67584

extern "C" void kernel_launch(void* const* d_in, const int* in_sizes, int n_in,
                              void* d_out, int out_size)
{
    const float* rel       = (const float*)d_in[0];
    const float* img       = (const float*)d_in[1];
    const int*   vox       = (const int*)d_in[2];
    const float* log_scale = (const float*)d_in[3];
    const float* shift     = (const float*)d_in[4];
    const float* log_sigma = (const float*)d_in[5];
    const float* w1  = (const float*)d_in[6];
    const float* c1b = (const float*)d_in[7];
    const float* g1  = (const float*)d_in[8];
    const float* b1  = (const float*)d_in[9];
    const float* m1  = (const float*)d_in[10];
    const float* v1  = (const float*)d_in[11];
    const float* w2  = (const float*)d_in[12];
    const float* c2b = (const float*)d_in[13];
    const float* g2  = (const float*)d_in[14];
    const float* b2  = (const float*)d_in[15];
    const float* m2  = (const float*)d_in[16];
    const float* v2  = (const float*)d_in[17];
    const float* w3  = (const float*)d_in[18];
    const float* c3b = (const float*)d_in[19];
    float* out = (float*)d_out;

    float *imgrp, *h1p, *h2p, *featp, *w1tp, *w2tp, *w3tp, *sc1p, *sc2p, *be1p, *be2p, *be3p;
    cudaGetSymbolAddress((void**)&imgrp, g_imgr);
    cudaGetSymbolAddress((void**)&h1p,   g_h1);
    cudaGetSymbolAddress((void**)&h2p,   g_h2);
    cudaGetSymbolAddress((void**)&featp, g_feat);
    cudaGetSymbolAddress((void**)&w1tp,  g_w1t);
    cudaGetSymbolAddress((void**)&w2tp,  g_w2t);
    cudaGetSymbolAddress((void**)&w3tp,  g_w3t);
    cudaGetSymbolAddress((void**)&sc1p,  g_scale1);
    cudaGetSymbolAddress((void**)&sc2p,  g_scale2);
    cudaGetSymbolAddress((void**)&be1p,  g_beta1);
    cudaGetSymbolAddress((void**)&be2p,  g_beta2);
    cudaGetSymbolAddress((void**)&be3p,  g_beta3);

    cudaFuncSetAttribute(conv_kernel<9, true, true>,
                         cudaFuncAttributeMaxDynamicSharedMemorySize, CONV_SMEM);
    cudaFuncSetAttribute(conv_kernel<1, false, false>,
                         cudaFuncAttributeMaxDynamicSharedMemorySize, CONV_SMEM);

    // launch order arranged so conv1 is launch #5 (captured by ncu -s 5 -c 1)
    zero_bev_kernel<<<2048, 256>>>();                                              // 0
    round_img_kernel<<<(NCAM * FCH * NPIX / 4 + 255) / 256, 256>>>(img, imgrp);    // 1
    setup_kernel<<<1, 256>>>(c1b, g1, b1, m1, v1, c2b, g2, b2, m2, v2, c3b);       // 2
    wtrans3x3_kernel<<<(9 * FCH * FCH + 255) / 256, 256>>>(w1, sc1p, w1tp);        // 3
    wtrans3x3_kernel<<<(9 * FCH * FCH + 255) / 256, 256>>>(w2, sc2p, w2tp);        // 4

    dim3 cgrid(NPIX / 128, FCH / 128, NCAM);     // (22, 2, 6)
    conv_kernel<9, true, true><<<cgrid, 256, CONV_SMEM>>>(imgrp, w1tp, be1p, h1p, FCH, FCH);  // 5

    wtrans1x1_kernel<<<(FCH * COUT + 255) / 256, 256>>>(w3, w3tp);                 // 6

    conv_kernel<9, true, true><<<cgrid, 256, CONV_SMEM>>>(h1p, w2tp, be2p, h2p, FCH, FCH);    // 7

    dim3 cgrid3(NPIX / 128, 1, NCAM);            // (22, 1, 6)
    conv_kernel<1, false, false><<<cgrid3, 256, CONV_SMEM>>>(h2p, w3tp, be3p, featp, FCH, COUT); // 8

    splat_kernel<<<NCAM * NPIX, 128>>>(rel, vox, log_scale, shift, log_sigma, featp);  // 9

    transpose_kernel<<<dim3(NVOX / 32, COUT / 32), dim3(32, 8)>>>(out);            // 10
}

// round 5
// speedup vs baseline: 1.7009x; 1.7009x over previous
#include <cuda_runtime.h>
#include <cuda_fp16.h>
#include <math.h>
#include <stdint.h>

#define FHH 32
#define FWW 88
#define NPIX 2816          // 32*88
#define NCAM 6
#define FCH 256            // conv channels
#define COUT 128           // BEV channels
#define ND 59              // depth bins
#define NVOX 16384         // 128*128 BEV cells

// ---------------- scratch (static device allocations) ----------------
__device__ __align__(16) __half g_imgh[NCAM * FCH * NPIX];   // fp16 NCHW input
__device__ __align__(16) __half g_h1h[NCAM * FCH * NPIX];    // fp16 NCHW
__device__ __align__(16) __half g_h2h[NCAM * FCH * NPIX];    // fp16 NCHW
__device__ __align__(16) float  g_feat[NCAM * COUT * NPIX];  // fp32 NCHW
__device__ __align__(16) __half g_w1h[9 * FCH * FCH];        // [t][ci][co] fp16
__device__ __align__(16) __half g_w2h[9 * FCH * FCH];
__device__ __align__(16) __half g_w3h[FCH * COUT];
__device__ float g_scale1[FCH], g_scale2[FCH];
__device__ float g_beta1[FCH], g_beta2[FCH], g_beta3[COUT];
__device__ __align__(16) float g_bev[NVOX * COUT];           // [vox][c]

// ---------------- helpers ----------------
__device__ __forceinline__ uint32_t smem_u32(const void* p) {
    uint32_t a;
    asm("{ .reg .u64 t; cvta.to.shared.u64 t, %1; cvt.u32.u64 %0, t; }" : "=r"(a) : "l"(p));
    return a;
}
__device__ __forceinline__ void ldsm4t(uint32_t* r, uint32_t addr) {
    asm volatile("ldmatrix.sync.aligned.m8n8.x4.trans.shared.b16 {%0,%1,%2,%3}, [%4];"
                 : "=r"(r[0]), "=r"(r[1]), "=r"(r[2]), "=r"(r[3]) : "r"(addr));
}
__device__ __forceinline__ void mma_f16(float* d, const uint32_t* a, uint32_t b0, uint32_t b1) {
    asm volatile(
        "mma.sync.aligned.m16n8k16.row.col.f32.f16.f16.f32 "
        "{%0,%1,%2,%3}, {%4,%5,%6,%7}, {%8,%9}, {%0,%1,%2,%3};\n"
        : "+f"(d[0]), "+f"(d[1]), "+f"(d[2]), "+f"(d[3])
        : "r"(a[0]), "r"(a[1]), "r"(a[2]), "r"(a[3]), "r"(b0), "r"(b1));
}

// ---------------- setup: fold BN into scale/beta ----------------
__global__ void setup_kernel(const float* __restrict__ c1b,
                             const float* __restrict__ g1, const float* __restrict__ b1,
                             const float* __restrict__ m1, const float* __restrict__ v1,
                             const float* __restrict__ c2b,
                             const float* __restrict__ g2, const float* __restrict__ b2,
                             const float* __restrict__ m2, const float* __restrict__ v2,
                             const float* __restrict__ c3b)
{
    int i = threadIdx.x;
    if (i < FCH) {
        float s1 = g1[i] * rsqrtf(v1[i] + 1e-3f);
        g_scale1[i] = s1;
        g_beta1[i] = (c1b[i] - m1[i]) * s1 + b1[i];
        float s2 = g2[i] * rsqrtf(v2[i] + 1e-3f);
        g_scale2[i] = s2;
        g_beta2[i] = (c2b[i] - m2[i]) * s2 + b2[i];
    }
    if (i < COUT) g_beta3[i] = c3b[i];
}

// ---------------- weight transforms: (Co,Ci,3,3)->[t][ci][co] fp16, scale folded ----------------
__global__ void wtrans3x3_kernel(const float* __restrict__ w,
                                 const float* __restrict__ scale,
                                 __half* __restrict__ out)
{
    int idx = blockIdx.x * blockDim.x + threadIdx.x;
    if (idx >= 9 * FCH * FCH) return;
    int t  = idx / (FCH * FCH);
    int r  = idx % (FCH * FCH);
    int ci = r / FCH;
    int co = r % FCH;
    out[idx] = __float2half_rn(w[(co * FCH + ci) * 9 + t] * scale[co]);
}

__global__ void wtrans1x1_kernel(const float* __restrict__ w, __half* __restrict__ out)
{
    int idx = blockIdx.x * blockDim.x + threadIdx.x;
    if (idx >= FCH * COUT) return;
    int ci = idx / COUT;
    int co = idx % COUT;
    out[idx] = __float2half_rn(w[co * FCH + ci]);
}

// ---------------- fp32 -> fp16 activation conversion ----------------
__global__ void round_img_kernel(const float* __restrict__ in, __half* __restrict__ out)
{
    int i = blockIdx.x * blockDim.x + threadIdx.x;
    if (i >= NCAM * FCH * NPIX / 4) return;
    float4 v = ((const float4*)in)[i];
    __half2 h0 = __floats2half2_rn(v.x, v.y);
    __half2 h1 = __floats2half2_rn(v.z, v.w);
    ((uint2*)out)[i] = make_uint2(*(uint32_t*)&h0, *(uint32_t*)&h1);
}

// ---------------- fp16 implicit-GEMM conv: mma.m16n8k16 + ldmatrix.trans ----------------
// Tile: BM=128 (co) x BN=128 (pixels), BK=32, 256 threads (8 warps, 2x4),
// warp tile 64co x 32pix = 2 ks x (4 mi x 4 ni) HMMA.16816.
// smem rows padded to 136 halves (272B = 17 x 16B segments -> conflict-free ldmatrix).
template <int TAPS, bool RELU, typename OutT>
__global__ void __launch_bounds__(256, 2)
conv_fp16_kernel(const __half* __restrict__ in_all, const __half* __restrict__ wtt,
                 const float* __restrict__ beta, OutT* __restrict__ out_all,
                 int Cin, int Cout)
{
    __shared__ __align__(16) __half As[32 * 136];   // [k][co]
    __shared__ __align__(16) __half Bs[32 * 136];   // [k][pix]
    const uint32_t abase = smem_u32(As);
    const uint32_t bbase = smem_u32(Bs);

    const int n   = blockIdx.z;
    const __half* in = in_all + (size_t)n * Cin * NPIX;
    OutT*        out = out_all + (size_t)n * Cout * NPIX;
    const int co0 = blockIdx.y * 128;
    const int p0  = blockIdx.x * 128;
    const int tid = threadIdx.x;
    const int lane = tid & 31;
    const int wid  = tid >> 5;
    const int wm0 = (wid & 1) * 64;
    const int wn0 = (wid >> 1) * 32;

    // B loader: one pixel column per thread, 16 k-rows
    const int pnB = tid & 127;
    const int kkB = tid >> 7;          // 0 or 1
    const int p  = p0 + pnB;
    const int hh = p / FWW;
    const int ww = p % FWW;

    const int KIT = Cin / 32;
    const int S = TAPS * KIT;

    float acc[4][4][4];
#pragma unroll
    for (int mi = 0; mi < 4; mi++)
#pragma unroll
        for (int ni = 0; ni < 4; ni++)
#pragma unroll
            for (int r = 0; r < 4; r++) acc[mi][ni][r] = 0.f;

    // ldmatrix lane address components
    const int grp = lane >> 3;         // matrix id 0..3
    const int row = lane & 7;
    // A mats: grp0:(k,m) grp1:(k,m+8) grp2:(k+8,m) grp3:(k+8,m+8)
    const int akr = ((grp & 2) ? 8 : 0) + row;
    const int amo = (grp & 1) ? 8 : 0;
    // B mats: grp0:(k,n) grp1:(k+8,n) grp2:(k,n+8) grp3:(k+8,n+8)
    const int bkr = ((grp & 1) ? 8 : 0) + row;
    const int bno = (grp & 2) ? 8 : 0;

    for (int s = 0; s < S; ++s) {
        const int t  = s / KIT;
        const int k0 = (s % KIT) * 32;

        // ---- stage A: 32k x 128co fp16 = 512 x 16B chunks ----
        {
            const __half* wt = wtt + (size_t)t * Cin * Cout;
#pragma unroll
            for (int i = 0; i < 2; i++) {
                int idx = tid + i * 256;          // 0..511
                int kk = idx >> 4;
                int seg = idx & 15;
                *(uint4*)((char*)As + kk * 272 + seg * 16) =
                    *(const uint4*)(wt + (size_t)(k0 + kk) * Cout + co0 + seg * 8);
            }
        }
        // ---- stage B: implicit-im2col, fp16 scalar with zero padding ----
        {
            bool valid;
            int srcoff;
            if (TAPS == 1) { valid = true; srcoff = p; }
            else {
                int dy = t / 3 - 1, dx = t % 3 - 1;
                int h2 = hh + dy, w2 = ww + dx;
                valid = (h2 >= 0) && (h2 < FHH) && (w2 >= 0) && (w2 < FWW);
                srcoff = valid ? h2 * FWW + w2 : 0;
            }
#pragma unroll
            for (int i = 0; i < 16; i++) {
                int kk = kkB + i * 2;
                __half v = valid ? in[(size_t)(k0 + kk) * NPIX + srcoff] : __half(0.f);
                Bs[kk * 136 + pnB] = v;
            }
        }
        __syncthreads();

        // ---- compute: 2 k16 steps ----
#pragma unroll
        for (int ks = 0; ks < 2; ks++) {
            const int kb = ks * 16;
            uint32_t a[4][4];
#pragma unroll
            for (int mi = 0; mi < 4; mi++) {
                int m = wm0 + mi * 16 + amo;
                ldsm4t(a[mi], abase + (uint32_t)((kb + akr) * 272 + m * 2));
            }
#pragma unroll
            for (int nip = 0; nip < 2; nip++) {
                int nn = wn0 + nip * 16 + bno;
                uint32_t b[4];
                ldsm4t(b, bbase + (uint32_t)((kb + bkr) * 272 + nn * 2));
#pragma unroll
                for (int mi = 0; mi < 4; mi++) {
                    mma_f16(acc[mi][nip * 2],     a[mi], b[0], b[1]);
                    mma_f16(acc[mi][nip * 2 + 1], a[mi], b[2], b[3]);
                }
            }
        }
        __syncthreads();
    }

    // ---- epilogue: +beta, relu, store (fp16 or fp32) ----
#pragma unroll
    for (int mi = 0; mi < 4; mi++) {
        int r0 = co0 + wm0 + mi * 16 + (lane >> 2);
        int r1 = r0 + 8;
        float be0 = beta[r0];
        float be1 = beta[r1];
#pragma unroll
        for (int ni = 0; ni < 4; ni++) {
            int c = p0 + wn0 + (ni >> 1) * 16 + (ni & 1) * 8 + (lane & 3) * 2;
            float v0 = acc[mi][ni][0] + be0;
            float v1 = acc[mi][ni][1] + be0;
            float v2 = acc[mi][ni][2] + be1;
            float v3 = acc[mi][ni][3] + be1;
            if (RELU) {
                v0 = fmaxf(v0, 0.f); v1 = fmaxf(v1, 0.f);
                v2 = fmaxf(v2, 0.f); v3 = fmaxf(v3, 0.f);
            }
            if (sizeof(OutT) == 2) {
                __half2 h0 = __floats2half2_rn(v0, v1);
                __half2 h1 = __floats2half2_rn(v2, v3);
                *(uint32_t*)((__half*)out + (size_t)r0 * NPIX + c) = *(uint32_t*)&h0;
                *(uint32_t*)((__half*)out + (size_t)r1 * NPIX + c) = *(uint32_t*)&h1;
            } else {
                *(float2*)((float*)out + (size_t)r0 * NPIX + c) = make_float2(v0, v1);
                *(float2*)((float*)out + (size_t)r1 * NPIX + c) = make_float2(v2, v3);
            }
        }
    }
}

// ---------------- zero the scratch BEV ----------------
__global__ void zero_bev_kernel()
{
    int idx = blockIdx.x * blockDim.x + threadIdx.x;
    float4 z = make_float4(0.f, 0.f, 0.f, 0.f);
    for (int i = idx; i < NVOX * COUT / 4; i += gridDim.x * blockDim.x)
        ((float4*)g_bev)[i] = z;
}

// ---------------- fused depth-softmax + lift + splat ----------------
__global__ void __launch_bounds__(128)
splat_kernel(const float* __restrict__ rel, const int* __restrict__ vox,
             const float* __restrict__ log_scale, const float* __restrict__ shift,
             const float* __restrict__ log_sigma, const float* __restrict__ feat)
{
    const int pb = blockIdx.x;
    const int n = pb / NPIX;
    const int p = pb % NPIX;
    const int tid = threadIdx.x;

    __shared__ float sw[ND];
    __shared__ int   sv[ND];
    __shared__ __align__(16) float sf[COUT];
    __shared__ float s_mx, s_inv;

    const float metric = fminf(fmaxf(expf(log_scale[0]) * rel[n * NPIX + p] + shift[0], 0.5f), 150.f);
    const float sigma  = fminf(fmaxf(expf(log_sigma[0]), 0.1f), 20.f);

    if (tid < ND) {
        sw[tid] = -fabsf(metric - (float)(tid + 1)) / sigma;
        sv[tid] = vox[(size_t)(n * ND + tid) * NPIX + p];
    }
    sf[tid] = feat[(size_t)(n * COUT + tid) * NPIX + p];
    __syncthreads();

    if (tid == 0) {
        float mx = -1e30f;
        for (int d = 0; d < ND; d++) mx = fmaxf(mx, sw[d]);
        float s = 0.f;
        for (int d = 0; d < ND; d++) s += expf(sw[d] - mx);
        s_mx = mx;
        s_inv = 1.f / s;
    }
    __syncthreads();
    if (tid < ND) sw[tid] = expf(sw[tid] - s_mx) * s_inv;
    __syncthreads();

    const int lane = tid & 31;
    const int wid  = tid >> 5;
    float4 f = *(const float4*)&sf[lane * 4];
    for (int d = wid; d < ND; d += 4) {
        float wg = sw[d];
        float4 v = make_float4(wg * f.x, wg * f.y, wg * f.z, wg * f.w);
        atomicAdd((float4*)&g_bev[(size_t)sv[d] * COUT + lane * 4], v);
    }
}

// ---------------- transpose [vox][c] -> output (C, X*Y) ----------------
__global__ void transpose_kernel(float* __restrict__ out)
{
    __shared__ float tile[32][33];
    int v0 = blockIdx.x * 32;
    int c0 = blockIdx.y * 32;
    int tx = threadIdx.x;
    int ty = threadIdx.y;
#pragma unroll
    for (int i = 0; i < 32; i += 8)
        tile[ty + i][tx] = g_bev[(size_t)(v0 + ty + i) * COUT + c0 + tx];
    __syncthreads();
#pragma unroll
    for (int i = 0; i < 32; i += 8)
        out[(size_t)(c0 + ty + i) * NVOX + v0 + tx] = tile[tx][ty + i];
}

// ---------------- launch ----------------
extern "C" void kernel_launch(void* const* d_in, const int* in_sizes, int n_in,
                              void* d_out, int out_size)
{
    const float* rel       = (const float*)d_in[0];
    const float* img       = (const float*)d_in[1];
    const int*   vox       = (const int*)d_in[2];
    const float* log_scale = (const float*)d_in[3];
    const float* shift     = (const float*)d_in[4];
    const float* log_sigma = (const float*)d_in[5];
    const float* w1  = (const float*)d_in[6];
    const float* c1b = (const float*)d_in[7];
    const float* g1  = (const float*)d_in[8];
    const float* b1  = (const float*)d_in[9];
    const float* m1  = (const float*)d_in[10];
    const float* v1  = (const float*)d_in[11];
    const float* w2  = (const float*)d_in[12];
    const float* c2b = (const float*)d_in[13];
    const float* g2  = (const float*)d_in[14];
    const float* b2  = (const float*)d_in[15];
    const float* m2  = (const float*)d_in[16];
    const float* v2  = (const float*)d_in[17];
    const float* w3  = (const float*)d_in[18];
    const float* c3b = (const float*)d_in[19];
    float* out = (float*)d_out;

    __half *imghp, *h1p, *h2p, *w1hp, *w2hp, *w3hp;
    float *featp, *sc1p, *sc2p, *be1p, *be2p, *be3p;
    cudaGetSymbolAddress((void**)&imghp, g_imgh);
    cudaGetSymbolAddress((void**)&h1p,   g_h1h);
    cudaGetSymbolAddress((void**)&h2p,   g_h2h);
    cudaGetSymbolAddress((void**)&featp, g_feat);
    cudaGetSymbolAddress((void**)&w1hp,  g_w1h);
    cudaGetSymbolAddress((void**)&w2hp,  g_w2h);
    cudaGetSymbolAddress((void**)&w3hp,  g_w3h);
    cudaGetSymbolAddress((void**)&sc1p,  g_scale1);
    cudaGetSymbolAddress((void**)&sc2p,  g_scale2);
    cudaGetSymbolAddress((void**)&be1p,  g_beta1);
    cudaGetSymbolAddress((void**)&be2p,  g_beta2);
    cudaGetSymbolAddress((void**)&be3p,  g_beta3);

    // launch order arranged so conv1 is launch #5 (captured by ncu -s 5 -c 1)
    zero_bev_kernel<<<2048, 256>>>();                                              // 0
    round_img_kernel<<<(NCAM * FCH * NPIX / 4 + 255) / 256, 256>>>(img, imghp);    // 1
    setup_kernel<<<1, 256>>>(c1b, g1, b1, m1, v1, c2b, g2, b2, m2, v2, c3b);       // 2
    wtrans3x3_kernel<<<(9 * FCH * FCH + 255) / 256, 256>>>(w1, sc1p, w1hp);        // 3
    wtrans3x3_kernel<<<(9 * FCH * FCH + 255) / 256, 256>>>(w2, sc2p, w2hp);        // 4

    dim3 cgrid(NPIX / 128, FCH / 128, NCAM);     // (22, 2, 6)
    conv_fp16_kernel<9, true, __half><<<cgrid, 256>>>(imghp, w1hp, be1p, h1p, FCH, FCH);   // 5

    wtrans1x1_kernel<<<(FCH * COUT + 255) / 256, 256>>>(w3, w3hp);                 // 6

    conv_fp16_kernel<9, true, __half><<<cgrid, 256>>>(h1p, w2hp, be2p, h2p, FCH, FCH);     // 7

    dim3 cgrid3(NPIX / 128, 1, NCAM);            // (22, 1, 6)
    conv_fp16_kernel<1, false, float><<<cgrid3, 256>>>(h2p, w3hp, be3p, featp, FCH, COUT); // 8

    splat_kernel<<<NCAM * NPIX, 128>>>(rel, vox, log_scale, shift, log_sigma, featp);      // 9

    transpose_kernel<<<dim3(NVOX / 32, COUT / 32), dim3(32, 8)>>>(out);            // 10
}